// round 15
// baseline (speedup 1.0000x reference)
#include <cuda_runtime.h>

// AudioDeviceModel_89008902242543  — R14
//
// s[b]      = dot(x[b,:], w1[0,:,0]) + b1+b2+b3+b4+b5
// out[b,d]  = s[b]*wd[d] + bd[d]            (B=8192, L=16384, D=128)
//
// HBM-read-bound: dot kernel is at the 512MB/6.86TB/s floor (~74.5us).
// R13's separate epilogue cost 4.4us (launch + load chain). R14 merges
// the epilogue into the dot tail via order-invariant atomics:
//   out = 0; split0 REDG-adds s0*wd[d]; split1 REDG-adds (s1+bias)*wd[d]+bd[d]
// IEEE addition is commutative, so 0 + c0 + c1 is bit-identical in either
// arrival order -> fully deterministic. No fences (no CCTL.IVALL), no
// g_partial round-trip. Upfront zero kernel is pure STG (~1.5us).

#define B_ROWS  8192
#define L_COLS  16384
#define L4      (L_COLS / 4)    // 4096 float4 per row
#define RPB     2               // rows per CTA
#define SPLIT   2               // column splits per row-pair
#define L4S     (L4 / SPLIT)    // 2048 float4 per split
#define NT      256
#define NWARPS  (NT / 32)
#define UNR     4               // column steps per batch
#define ITERS   (L4S / NT)      // 8 -> 2 batches of UNR
#define OUT_F4  (B_ROWS * 128 / 4)   // 262144 float4 in out

__device__ __forceinline__ float dot4_acc(float4 xx, float4 w, float a) {
    return fmaf(xx.x, w.x, fmaf(xx.y, w.y, fmaf(xx.z, w.z, fmaf(xx.w, w.w, a))));
}

__global__ __launch_bounds__(NT)
void zero_out_kernel(float4* __restrict__ out4)
{
    // 1024 CTAs x 256 threads x 1 float4: pure coalesced STG.128, no loads.
    out4[blockIdx.x * NT + threadIdx.x] = make_float4(0.f, 0.f, 0.f, 0.f);
}

__global__ __launch_bounds__(NT, 4)
void audio_dot_kernel(const float* __restrict__ x,
                      const float* __restrict__ w1,
                      const float* __restrict__ b1,
                      const float* __restrict__ b2,
                      const float* __restrict__ b3,
                      const float* __restrict__ b4,
                      const float* __restrict__ b5,
                      const float* __restrict__ wd,
                      const float* __restrict__ bd,
                      float* __restrict__ out)
{
    const int pair  = blockIdx.x >> 1;       // row-pair index
    const int split = blockIdx.x & 1;        // column half
    const int b0    = pair * RPB;
    const int tid   = threadIdx.x;

    const float4* __restrict__ wv = reinterpret_cast<const float4*>(w1);
    const float4* __restrict__ xv =
        reinterpret_cast<const float4*>(x) + (size_t)b0 * L4;

    float acc[RPB];
#pragma unroll
    for (int r = 0; r < RPB; r++) acc[r] = 0.0f;

    int i = split * L4S + tid;
#pragma unroll 1
    for (int it = 0; it < ITERS; it += UNR, i += UNR * NT) {
        // Front-batch the 8 HBM loads (2 rows x 4 column steps).
        float4 xx[RPB][UNR];
#pragma unroll
        for (int u = 0; u < UNR; u++)
#pragma unroll
            for (int r = 0; r < RPB; r++)
                xx[r][u] = __ldcs(&xv[(size_t)r * L4 + i + u * NT]);

        // w loads are L2 hits; JIT to save registers.
#pragma unroll
        for (int u = 0; u < UNR; u++) {
            float4 w = wv[i + u * NT];
#pragma unroll
            for (int r = 0; r < RPB; r++)
                acc[r] = dot4_acc(xx[r][u], w, acc[r]);
        }
    }

    // Intra-warp tree reduction for each row accumulator.
#pragma unroll
    for (int r = 0; r < RPB; r++) {
#pragma unroll
        for (int off = 16; off > 0; off >>= 1)
            acc[r] += __shfl_xor_sync(0xffffffffu, acc[r], off);
    }

    __shared__ float part[NWARPS][RPB];
    __shared__ float srow[RPB];

    const int wid = tid >> 5;
    const int lid = tid & 31;
    if (lid == 0) {
#pragma unroll
        for (int r = 0; r < RPB; r++) part[wid][r] = acc[r];
    }
    __syncthreads();

    if (tid < RPB) {
        float s = 0.0f;
#pragma unroll
        for (int w = 0; w < NWARPS; w++) s += part[w][tid];
        // split1 carries the bias term so the two contributions sum to the
        // full result.
        if (split == 1)
            s += b1[0] + b2[0] + b3[0] + b4[0] + b5[0];
        srow[tid] = s;
    }
    __syncthreads();

    // Tail: each split CTA REDG-adds its complete contribution.
    //   split0: s0*wd[d]      split1: (s1+bias)*wd[d] + bd[d]
    // out starts at exactly 0.0 -> commutative adds -> deterministic.
    {
        const int r = tid >> 7;          // 0..1
        const int d = tid & 127;
        float contrib = srow[r] * wd[d];
        if (split == 1) contrib += bd[d];
        atomicAdd(&out[(size_t)(b0 + r) * 128 + d], contrib);
    }
}

extern "C" void kernel_launch(void* const* d_in, const int* in_sizes, int n_in,
                              void* d_out, int out_size)
{
    // metadata order: x, w1, b1, w2, b2, w3, b3, w4, b4, w5, b5, wd, bd
    const float* x  = (const float*)d_in[0];
    const float* w1 = (const float*)d_in[1];
    const float* b1 = (const float*)d_in[2];
    const float* b2 = (const float*)d_in[4];
    const float* b3 = (const float*)d_in[6];
    const float* b4 = (const float*)d_in[8];
    const float* b5 = (const float*)d_in[10];
    const float* wd = (const float*)d_in[11];
    const float* bd = (const float*)d_in[12];
    float* out = (float*)d_out;

    zero_out_kernel<<<OUT_F4 / NT, NT>>>(reinterpret_cast<float4*>(out));

    dim3 grid((B_ROWS / RPB) * SPLIT);   // 8192 CTAs (half row-pairs)
    audio_dot_kernel<<<grid, NT>>>(x, w1, b1, b2, b3, b4, b5, wd, bd, out);
}

// round 17
// speedup vs baseline: 1.0227x; 1.0227x over previous
#include <cuda_runtime.h>

// AudioDeviceModel_89008902242543  — R15
//
// s[b]      = dot(x[b,:], w1[0,:,0]) + b1+b2+b3+b4+b5
// out[b,d]  = s[b]*wd[d] + bd[d]            (B=8192, L=16384, D=128)
//
// Dot kernel sits at the HBM floor (512 MB @ ~6.86 TB/s ~= 74.5us).
// R14's atomic-merge regressed (extra bytes + RMW tail). R15 = R13's
// proven split-K dot + one-wave epilogue, with PDL: the epilogue is
// launched programmatically so its CTAs start during the dot kernel's
// ramp-down, run their independent prologue (bias/wd/bd cold loads),
// then cudaGridDependencySynchronize() gates the g_partial reads.

#define B_ROWS  8192
#define L_COLS  16384
#define L4      (L_COLS / 4)    // 4096 float4 per row
#define RPB     2               // rows per CTA
#define SPLIT   2               // column splits per row-pair
#define L4S     (L4 / SPLIT)    // 2048 float4 per split
#define NT      256
#define NWARPS  (NT / 32)
#define UNR     4               // column steps per batch
#define ITERS   (L4S / NT)      // 8 -> 2 batches of UNR

__device__ float g_partial[B_ROWS * SPLIT];

__device__ __forceinline__ float dot4_acc(float4 xx, float4 w, float a) {
    return fmaf(xx.x, w.x, fmaf(xx.y, w.y, fmaf(xx.z, w.z, fmaf(xx.w, w.w, a))));
}

__global__ __launch_bounds__(NT, 4)
void audio_dot_kernel(const float* __restrict__ x,
                      const float* __restrict__ w1)
{
    // Allow the dependent epilogue grid to begin launching once every CTA
    // of this grid has started (it still waits on full completion before
    // touching g_partial, via cudaGridDependencySynchronize).
    cudaTriggerProgrammaticLaunchCompletion();

    const int pair  = blockIdx.x >> 1;       // row-pair index
    const int split = blockIdx.x & 1;        // column half
    const int b0    = pair * RPB;
    const int tid   = threadIdx.x;

    const float4* __restrict__ wv = reinterpret_cast<const float4*>(w1);
    const float4* __restrict__ xv =
        reinterpret_cast<const float4*>(x) + (size_t)b0 * L4;

    float acc[RPB];
#pragma unroll
    for (int r = 0; r < RPB; r++) acc[r] = 0.0f;

    int i = split * L4S + tid;
#pragma unroll 1
    for (int it = 0; it < ITERS; it += UNR, i += UNR * NT) {
        // Front-batch the 8 HBM loads (2 rows x 4 column steps).
        float4 xx[RPB][UNR];
#pragma unroll
        for (int u = 0; u < UNR; u++)
#pragma unroll
            for (int r = 0; r < RPB; r++)
                xx[r][u] = __ldcs(&xv[(size_t)r * L4 + i + u * NT]);

        // w loads are L2 hits; JIT to save registers.
#pragma unroll
        for (int u = 0; u < UNR; u++) {
            float4 w = wv[i + u * NT];
#pragma unroll
            for (int r = 0; r < RPB; r++)
                acc[r] = dot4_acc(xx[r][u], w, acc[r]);
        }
    }

    // Intra-warp tree reduction for each row accumulator.
#pragma unroll
    for (int r = 0; r < RPB; r++) {
#pragma unroll
        for (int off = 16; off > 0; off >>= 1)
            acc[r] += __shfl_xor_sync(0xffffffffu, acc[r], off);
    }

    __shared__ float part[NWARPS][RPB];
    const int wid = tid >> 5;
    const int lid = tid & 31;
    if (lid == 0) {
#pragma unroll
        for (int r = 0; r < RPB; r++) part[wid][r] = acc[r];
    }
    __syncthreads();

    if (tid < RPB) {
        float s = 0.0f;
#pragma unroll
        for (int w = 0; w < NWARPS; w++) s += part[w][tid];
        g_partial[(b0 + tid) * SPLIT + split] = s;   // deterministic slot
    }
}

__global__ __launch_bounds__(NT)
void audio_epilogue_kernel(const float* __restrict__ b1,
                           const float* __restrict__ b2,
                           const float* __restrict__ b3,
                           const float* __restrict__ b4,
                           const float* __restrict__ b5,
                           const float* __restrict__ wd,
                           const float* __restrict__ bd,
                           float* __restrict__ out)
{
    // One float4 (4 output cols) per thread: 8192 rows x 32 float4 =
    // 1024 CTAs x 256 threads. Launched via PDL: the prologue below
    // (independent of the dot kernel's output) overlaps the dot tail.
    const int gid = blockIdx.x * NT + threadIdx.x;
    const int row = gid >> 5;        // 32 float4 per row
    const int c4  = gid & 31;

    // --- prologue: loads independent of g_partial ---
    const float4 w = reinterpret_cast<const float4*>(wd)[c4];
    const float4 b = reinterpret_cast<const float4*>(bd)[c4];
    const float bias = b1[0] + b2[0] + b3[0] + b4[0] + b5[0];

    // --- gate: wait for the dot grid to fully complete ---
    cudaGridDependencySynchronize();

    // Fixed order (split0 + split1) -> bit-deterministic.
    const float s = g_partial[row * SPLIT + 0]
                  + g_partial[row * SPLIT + 1] + bias;

    float4 o;
    o.x = fmaf(s, w.x, b.x);
    o.y = fmaf(s, w.y, b.y);
    o.z = fmaf(s, w.z, b.z);
    o.w = fmaf(s, w.w, b.w);
    reinterpret_cast<float4*>(out)[gid] = o;
}

extern "C" void kernel_launch(void* const* d_in, const int* in_sizes, int n_in,
                              void* d_out, int out_size)
{
    // metadata order: x, w1, b1, w2, b2, w3, b3, w4, b4, w5, b5, wd, bd
    const float* x  = (const float*)d_in[0];
    const float* w1 = (const float*)d_in[1];
    const float* b1 = (const float*)d_in[2];
    const float* b2 = (const float*)d_in[4];
    const float* b3 = (const float*)d_in[6];
    const float* b4 = (const float*)d_in[8];
    const float* b5 = (const float*)d_in[10];
    const float* wd = (const float*)d_in[11];
    const float* bd = (const float*)d_in[12];
    float* out = (float*)d_out;

    dim3 gridA((B_ROWS / RPB) * SPLIT);           // 8192 CTAs
    audio_dot_kernel<<<gridA, NT>>>(x, w1);

    // Epilogue with programmatic dependent launch (overlaps dot tail).
    cudaLaunchConfig_t cfg = {};
    cfg.gridDim  = dim3((B_ROWS * 128 / 4) / NT); // 1024 CTAs
    cfg.blockDim = dim3(NT);
    cfg.dynamicSmemBytes = 0;
    cfg.stream = 0;
    cudaLaunchAttribute attr[1];
    attr[0].id = cudaLaunchAttributeProgrammaticStreamSerialization;
    attr[0].val.programmaticStreamSerializationAllowed = 1;
    cfg.attrs = attr;
    cfg.numAttrs = 1;
    cudaLaunchKernelEx(&cfg, audio_epilogue_kernel,
                       b1, b2, b3, b4, b5, wd, bd, out);
}